// round 1
// baseline (speedup 1.0000x reference)
#include <cuda_runtime.h>
#include <cuda_bf16.h>

// Problem constants (from reference): B=4096 batch, T=4 tasks, D=1024 dim,
// L=2 layers, E=4 experts/task.
#define BB 4096
#define TT 4
#define DD 1024
#define LL 2
#define EE 4

// -------- scratch (allocation-free: __device__ globals) --------
__device__ float g_t1 [BB * TT * DD];  // stage-1 activations
__device__ float g_teo[BB * TT * DD];  // stage-2 (scaled) activations
__device__ float g_h  [BB * TT * DD];  // inter-layer hidden state

// ============================================================================
// Batched GEMM: for task t (blockIdx.z), Y[b, t, :] = act( A[b, t, :] @ W_t + bias_t )
// A is [B, T, D] (row for (b,t) at (b*T+t)*D), W_t is [D, D] row-major (d -> o),
// Y is [B, T, D]. Epilogue: +bias, ReLU, then optional scale = sum_e inte[t, e].
// Classic 128x128x8 tile, 256 threads, 8x8 per-thread micro-tile, float4 I/O.
// ============================================================================
#define BM 128
#define BN 128
#define BK 8
#define TM 8
#define TN 8

__global__ __launch_bounds__(256, 2)
void gemm_bias_relu(const float* __restrict__ A,     // [B, T, D]
                    const float* __restrict__ W,     // [T, D, D] (per-task weights for this layer)
                    const float* __restrict__ bias,  // [T, D]
                    const float* __restrict__ inte,  // [T, E] or nullptr
                    float* __restrict__ Y)           // [B, T, D]
{
    const int task = blockIdx.z;
    const int m0 = blockIdx.y * BM;   // batch-row block
    const int n0 = blockIdx.x * BN;   // output-col block

    const float* Wt = W + (size_t)task * DD * DD;
    const float* bt = bias + (size_t)task * DD;

    __shared__ float As[BK][BM];      // transposed A tile
    __shared__ float Bs[BK][BN];

    const int tid = threadIdx.x;      // 0..255
    const int tx  = tid & 15;         // 0..15  -> cols (TN*16 = 128)
    const int ty  = tid >> 4;         // 0..15  -> rows (TM*16 = 128)

    // A-tile load mapping: 128 rows x 8 cols = 1024 floats = 256 x float4
    const int aRow  = tid >> 1;            // 0..127
    const int aCol4 = (tid & 1) * 4;       // 0 or 4
    // B-tile load mapping: 8 rows x 128 cols = 256 x float4
    const int bRow  = tid >> 5;            // 0..7
    const int bCol4 = (tid & 31) * 4;      // 0..124

    float acc[TM][TN];
    #pragma unroll
    for (int i = 0; i < TM; i++)
        #pragma unroll
        for (int j = 0; j < TN; j++) acc[i][j] = 0.0f;

    const size_t a_row_base = ((size_t)(m0 + aRow) * TT + task) * DD;

    for (int k0 = 0; k0 < DD; k0 += BK) {
        // load A tile (transposed into smem)
        float4 a4 = *reinterpret_cast<const float4*>(A + a_row_base + k0 + aCol4);
        As[aCol4 + 0][aRow] = a4.x;
        As[aCol4 + 1][aRow] = a4.y;
        As[aCol4 + 2][aRow] = a4.z;
        As[aCol4 + 3][aRow] = a4.w;
        // load B tile
        float4 b4 = *reinterpret_cast<const float4*>(Wt + (size_t)(k0 + bRow) * DD + n0 + bCol4);
        *reinterpret_cast<float4*>(&Bs[bRow][bCol4]) = b4;
        __syncthreads();

        #pragma unroll
        for (int k = 0; k < BK; k++) {
            float a[TM], b[TN];
            float4 a0 = *reinterpret_cast<const float4*>(&As[k][ty * TM]);
            float4 a1 = *reinterpret_cast<const float4*>(&As[k][ty * TM + 4]);
            a[0]=a0.x; a[1]=a0.y; a[2]=a0.z; a[3]=a0.w;
            a[4]=a1.x; a[5]=a1.y; a[6]=a1.z; a[7]=a1.w;
            float4 b0 = *reinterpret_cast<const float4*>(&Bs[k][tx * TN]);
            float4 b1 = *reinterpret_cast<const float4*>(&Bs[k][tx * TN + 4]);
            b[0]=b0.x; b[1]=b0.y; b[2]=b0.z; b[3]=b0.w;
            b[4]=b1.x; b[5]=b1.y; b[6]=b1.z; b[7]=b1.w;
            #pragma unroll
            for (int i = 0; i < TM; i++)
                #pragma unroll
                for (int j = 0; j < TN; j++)
                    acc[i][j] = fmaf(a[i], b[j], acc[i][j]);
        }
        __syncthreads();
    }

    // epilogue: +bias, ReLU, optional scale (sum of E integration weights)
    float scale = 1.0f;
    if (inte != nullptr) {
        const float* it = inte + task * EE;
        scale = it[0] + it[1] + it[2] + it[3];
    }

    #pragma unroll
    for (int i = 0; i < TM; i++) {
        const int m = m0 + ty * TM + i;
        const size_t y_base = ((size_t)m * TT + task) * DD + n0 + tx * TN;
        #pragma unroll
        for (int j = 0; j < TN; j += 4) {
            float4 v;
            v.x = fmaxf(acc[i][j+0] + bt[n0 + tx*TN + j+0], 0.0f) * scale;
            v.y = fmaxf(acc[i][j+1] + bt[n0 + tx*TN + j+1], 0.0f) * scale;
            v.z = fmaxf(acc[i][j+2] + bt[n0 + tx*TN + j+2], 0.0f) * scale;
            v.w = fmaxf(acc[i][j+3] + bt[n0 + tx*TN + j+3], 0.0f) * scale;
            *reinterpret_cast<float4*>(const_cast<float*>(Y + y_base + j)) = v;
        }
    }
}

// ============================================================================
// Gate + combine: per batch element b:
//   logits[t,k] = teo[b,t,:] . Wg[:,k] + bg[k];  g = softmax_k(logits)
//   out[b,t,:]  = teo[b,t,:] + sum_k g[t,k] * teo[b,k,:]
// One block (128 threads) per b. Warp w computes row t=w of the 4x4 gate.
// ============================================================================
__global__ __launch_bounds__(128)
void gate_combine(const float* __restrict__ teo,  // [B, T, D]
                  const float* __restrict__ Wg,   // [D, T]
                  const float* __restrict__ bg,   // [T]
                  float* __restrict__ out)        // [B, T, D]
{
    const int b = blockIdx.x;
    __shared__ float s_teo[TT][DD];   // 16 KB
    __shared__ float s_g[TT][TT];

    const int tid  = threadIdx.x;
    const int warp = tid >> 5;
    const int lane = tid & 31;

    const size_t base = (size_t)b * TT * DD;
    // stage teo[b] into smem (float4)
    for (int idx = tid; idx < TT * DD / 4; idx += 128) {
        reinterpret_cast<float4*>(&s_teo[0][0])[idx] =
            reinterpret_cast<const float4*>(teo + base)[idx];
    }
    __syncthreads();

    // each warp: 4 dots of length D for its task row
    float acc0 = 0.f, acc1 = 0.f, acc2 = 0.f, acc3 = 0.f;
    for (int d = lane; d < DD; d += 32) {
        float v = s_teo[warp][d];
        float4 w = reinterpret_cast<const float4*>(Wg)[d];  // Wg[d*4 + 0..3]
        acc0 = fmaf(v, w.x, acc0);
        acc1 = fmaf(v, w.y, acc1);
        acc2 = fmaf(v, w.z, acc2);
        acc3 = fmaf(v, w.w, acc3);
    }
    #pragma unroll
    for (int off = 16; off; off >>= 1) {
        acc0 += __shfl_xor_sync(0xffffffffu, acc0, off);
        acc1 += __shfl_xor_sync(0xffffffffu, acc1, off);
        acc2 += __shfl_xor_sync(0xffffffffu, acc2, off);
        acc3 += __shfl_xor_sync(0xffffffffu, acc3, off);
    }
    if (lane == 0) {
        float l0 = acc0 + bg[0], l1 = acc1 + bg[1], l2 = acc2 + bg[2], l3 = acc3 + bg[3];
        float m = fmaxf(fmaxf(l0, l1), fmaxf(l2, l3));
        float e0 = __expf(l0 - m), e1 = __expf(l1 - m), e2 = __expf(l2 - m), e3 = __expf(l3 - m);
        float inv = 1.0f / (e0 + e1 + e2 + e3);
        s_g[warp][0] = e0 * inv;
        s_g[warp][1] = e1 * inv;
        s_g[warp][2] = e2 * inv;
        s_g[warp][3] = e3 * inv;
    }
    __syncthreads();

    // combine + residual
    #pragma unroll
    for (int t = 0; t < TT; t++) {
        const float g0 = s_g[t][0], g1 = s_g[t][1], g2 = s_g[t][2], g3 = s_g[t][3];
        for (int d = tid; d < DD; d += 128) {
            float r = s_teo[t][d];
            r = fmaf(g0, s_teo[0][d], r);
            r = fmaf(g1, s_teo[1][d], r);
            r = fmaf(g2, s_teo[2][d], r);
            r = fmaf(g3, s_teo[3][d], r);
            out[base + (size_t)t * DD + d] = r;
        }
    }
}

// ============================================================================
// launch
// ============================================================================
extern "C" void kernel_launch(void* const* d_in, const int* in_sizes, int n_in,
                              void* d_out, int out_size)
{
    const float* x    = (const float*)d_in[0];
    const float* W1   = (const float*)d_in[1];
    const float* b1   = (const float*)d_in[2];
    const float* W2   = (const float*)d_in[3];
    const float* b2   = (const float*)d_in[4];
    const float* inte = (const float*)d_in[5];
    const float* Wg   = (const float*)d_in[6];
    const float* bg   = (const float*)d_in[7];
    float* out = (float*)d_out;

    float *t1, *teo, *h;
    cudaGetSymbolAddress((void**)&t1,  g_t1);
    cudaGetSymbolAddress((void**)&teo, g_teo);
    cudaGetSymbolAddress((void**)&h,   g_h);

    dim3 gemm_grid(DD / BN, BB / BM, TT);   // (8, 32, 4)
    dim3 gemm_blk(256);

    const float* layer_in = x;
    for (int l = 0; l < LL; l++) {
        const float* W1l = W1 + (size_t)l * TT * DD * DD;
        const float* b1l = b1 + (size_t)l * TT * DD;
        const float* W2l = W2 + (size_t)l * TT * DD * DD;
        const float* b2l = b2 + (size_t)l * TT * DD;
        const float* il  = inte + (size_t)l * TT * EE;
        const float* Wgl = Wg + (size_t)l * DD * TT;
        const float* bgl = bg + (size_t)l * TT;

        gemm_bias_relu<<<gemm_grid, gemm_blk>>>(layer_in, W1l, b1l, nullptr, t1);
        gemm_bias_relu<<<gemm_grid, gemm_blk>>>(t1, W2l, b2l, il, teo);

        float* gate_out = (l == LL - 1) ? out : h;
        gate_combine<<<BB, 128>>>(teo, Wgl, bgl, gate_out);
        layer_in = h;
    }
}

// round 3
// speedup vs baseline: 2.7864x; 2.7864x over previous
#include <cuda_runtime.h>
#include <cuda_bf16.h>
#include <cstdint>

// Problem constants: B=4096 batch, T=4 tasks, D=1024 dim, L=2 layers, E=4.
#define BB 4096
#define TT 4
#define DD 1024
#define LL 2
#define EE 4

// GEMM tiling
#define BM 128            // batch rows / CTA
#define BN 128            // output cols / CTA
#define KC 64             // k per chunk (bf16 elems)
#define NCHUNK (DD / KC)  // 16

// SMEM stage layout:
//   Ahi [128m][128B] 16384   (SW128 swizzled, K-major)
//   Alo                +16384
//   Bhi [64k][272B]  17408   (padded rows, N contiguous)
//   Blo                +17408
#define A_PITCH 128
#define B_PITCH 272
#define A_BYTES (BM * A_PITCH)       // 16384
#define B_BYTES (KC * B_PITCH)       // 17408
#define OFF_AHI 0
#define OFF_ALO A_BYTES
#define OFF_BHI (2 * A_BYTES)
#define OFF_BLO (2 * A_BYTES + B_BYTES)
#define STAGE   (2 * A_BYTES + 2 * B_BYTES)   // 67584
#define SMEM_TOTAL (2 * STAGE)                // 135168

#define SW128(x) ((x) ^ (((x) >> 3) & 0x70))

// -------- scratch (allocation-free: __device__ globals) --------
__device__ float g_t1 [BB * TT * DD];
__device__ float g_teo[BB * TT * DD];
__device__ float g_h  [BB * TT * DD];

// ---------------------------------------------------------------------------
__device__ __forceinline__ uint32_t smem_u32(const void* p) {
    uint32_t a;
    asm("{ .reg .u64 t; cvta.to.shared.u64 t, %1; cvt.u32.u64 %0, t; }"
        : "=r"(a) : "l"(p));
    return a;
}

__device__ __forceinline__ void ldsm_x4(uint32_t& r0, uint32_t& r1,
                                        uint32_t& r2, uint32_t& r3,
                                        uint32_t addr) {
    asm volatile("ldmatrix.sync.aligned.m8n8.x4.shared.b16 {%0,%1,%2,%3}, [%4];"
                 : "=r"(r0), "=r"(r1), "=r"(r2), "=r"(r3) : "r"(addr));
}

__device__ __forceinline__ void ldsm_x2t(uint32_t& r0, uint32_t& r1,
                                         uint32_t addr) {
    asm volatile("ldmatrix.sync.aligned.m8n8.x2.trans.shared.b16 {%0,%1}, [%2];"
                 : "=r"(r0), "=r"(r1) : "r"(addr));
}

__device__ __forceinline__ void mma_bf16(float* c, const uint32_t* a,
                                         const uint32_t* b) {
    asm volatile(
        "mma.sync.aligned.m16n8k16.row.col.f32.bf16.bf16.f32 "
        "{%0,%1,%2,%3}, {%4,%5,%6,%7}, {%8,%9}, {%0,%1,%2,%3};"
        : "+f"(c[0]), "+f"(c[1]), "+f"(c[2]), "+f"(c[3])
        : "r"(a[0]), "r"(a[1]), "r"(a[2]), "r"(a[3]), "r"(b[0]), "r"(b[1]));
}

// split fp32 pair -> (hi bf16x2, lo bf16x2). hi = truncation (exact in fp32).
__device__ __forceinline__ void split_pair(float v0, float v1,
                                           uint32_t& hp, uint32_t& lp) {
    uint32_t u0 = __float_as_uint(v0), u1 = __float_as_uint(v1);
    hp = (u0 >> 16) | (u1 & 0xFFFF0000u);
    float r0 = v0 - __uint_as_float(u0 & 0xFFFF0000u);
    float r1 = v1 - __uint_as_float(u1 & 0xFFFF0000u);
    __nv_bfloat162 l2 = __floats2bfloat162_rn(r0, r1);
    lp = *reinterpret_cast<uint32_t*>(&l2);
}

// ============================================================================
// bf16-split mma.sync GEMM: Y[b,t,:] = relu(A[b,t,:] @ W_t + bias_t) * scale_t
// ============================================================================
__global__ __launch_bounds__(256, 1)
void gemm_mma(const float* __restrict__ A,     // [B, T, D]
              const float* __restrict__ W,     // [T, D, D]   (d -> o)
              const float* __restrict__ bias,  // [T, D]
              const float* __restrict__ inte,  // [T, E] or nullptr
              float* __restrict__ Y)           // [B, T, D]
{
    extern __shared__ char smem[];
    const uint32_t sbase = smem_u32(smem);

    const int tid  = threadIdx.x;
    const int warp = tid >> 5;
    const int lane = tid & 31;
    const int task = blockIdx.z;
    const int m0   = blockIdx.y * BM;
    const int n0   = blockIdx.x * BN;

    const float* Wt = W + (size_t)task * DD * DD;
    const float* bt = bias + (size_t)task * DD;

    const int wm = warp & 1;    // 0..1  (64-row groups)
    const int wn = warp >> 1;   // 0..3  (32-col groups)

    // ---- per-thread load index maps (constant across chunks) ----
    // A: 8 float4/thread; it -> element (m, k4)
    int a_m[8], a_k4[8];
    // B: 8 float4/thread; it -> element (k, n4)
    int b_k[8], b_n4[8];
    #pragma unroll
    for (int it = 0; it < 8; ++it) {
        int idx = it * 256 + tid;
        a_m[it]  = idx >> 4;        // 0..127
        a_k4[it] = idx & 15;        // 0..15 (float4 along k)
        b_k[it]  = idx >> 5;        // 0..63
        b_n4[it] = idx & 31;        // 0..31 (float4 along n)
    }

    float4 ra[8], rb[8];

    // ---- LDG of one K-chunk into registers ----
    auto ldg_chunk = [&](int k0) {
        #pragma unroll
        for (int it = 0; it < 8; ++it) {
            ra[it] = *reinterpret_cast<const float4*>(
                A + ((size_t)(m0 + a_m[it]) * TT + task) * DD + k0 + a_k4[it] * 4);
            rb[it] = *reinterpret_cast<const float4*>(
                Wt + (size_t)(k0 + b_k[it]) * DD + n0 + b_n4[it] * 4);
        }
    };

    // ---- convert + STS one chunk from registers ----
    auto sts_chunk = [&](char* st) {
        #pragma unroll
        for (int it = 0; it < 8; ++it) {
            uint32_t hp0, lp0, hp1, lp1;
            split_pair(ra[it].x, ra[it].y, hp0, lp0);
            split_pair(ra[it].z, ra[it].w, hp1, lp1);
            uint32_t off = SW128((uint32_t)(a_m[it] * A_PITCH + a_k4[it] * 8));
            *reinterpret_cast<uint64_t*>(st + OFF_AHI + off) =
                (uint64_t)hp0 | ((uint64_t)hp1 << 32);
            *reinterpret_cast<uint64_t*>(st + OFF_ALO + off) =
                (uint64_t)lp0 | ((uint64_t)lp1 << 32);
        }
        #pragma unroll
        for (int it = 0; it < 8; ++it) {
            uint32_t hp0, lp0, hp1, lp1;
            split_pair(rb[it].x, rb[it].y, hp0, lp0);
            split_pair(rb[it].z, rb[it].w, hp1, lp1);
            uint32_t off = (uint32_t)(b_k[it] * B_PITCH + b_n4[it] * 8);
            *reinterpret_cast<uint64_t*>(st + OFF_BHI + off) =
                (uint64_t)hp0 | ((uint64_t)hp1 << 32);
            *reinterpret_cast<uint64_t*>(st + OFF_BLO + off) =
                (uint64_t)lp0 | ((uint64_t)lp1 << 32);
        }
    };

    // ---- accumulators ----
    float acc[4][4][4];
    #pragma unroll
    for (int i = 0; i < 4; ++i)
        #pragma unroll
        for (int j = 0; j < 4; ++j)
            #pragma unroll
            for (int r = 0; r < 4; ++r) acc[i][j][r] = 0.0f;

    // ldmatrix lane-address components (constant)
    // A (non-trans, x4): rows m_frag + (lane&15), col bytes ks*32 + ((lane>>4)<<4)
    const int a_lrow = lane & 15;
    const int a_lcol = (lane >> 4) << 4;
    // B (trans, x2): rows k = ks*16 + (lane&15), col = n-frag byte offset
    const int b_lrow = lane & 15;

    // ---- prologue ----
    ldg_chunk(0);
    sts_chunk(smem);
    ldg_chunk(KC);
    __syncthreads();

    for (int chunk = 0; chunk < NCHUNK; ++chunk) {
        char* st = smem + (chunk & 1) * STAGE;
        const uint32_t stb = sbase + (chunk & 1) * STAGE;

        // ---- MMA phase on stage (chunk & 1) ----
        #pragma unroll
        for (int ks = 0; ks < 4; ++ks) {
            uint32_t ah[4][4], al[4][4], bh[4][2], bl[4][2];
            #pragma unroll
            for (int mf = 0; mf < 4; ++mf) {
                int row = wm * 64 + mf * 16 + a_lrow;
                uint32_t off = SW128((uint32_t)(row * A_PITCH + ks * 32 + a_lcol));
                ldsm_x4(ah[mf][0], ah[mf][1], ah[mf][2], ah[mf][3],
                        stb + OFF_AHI + off);
                ldsm_x4(al[mf][0], al[mf][1], al[mf][2], al[mf][3],
                        stb + OFF_ALO + off);
            }
            #pragma unroll
            for (int nf = 0; nf < 4; ++nf) {
                int ncol = wn * 32 + nf * 8;
                uint32_t off = (uint32_t)((ks * 16 + b_lrow) * B_PITCH + ncol * 2);
                ldsm_x2t(bh[nf][0], bh[nf][1], stb + OFF_BHI + off);
                ldsm_x2t(bl[nf][0], bl[nf][1], stb + OFF_BLO + off);
            }
            #pragma unroll
            for (int mf = 0; mf < 4; ++mf)
                #pragma unroll
                for (int nf = 0; nf < 4; ++nf) {
                    mma_bf16(acc[mf][nf], ah[mf], bh[nf]);
                    mma_bf16(acc[mf][nf], ah[mf], bl[nf]);
                    mma_bf16(acc[mf][nf], al[mf], bh[nf]);
                }
        }

        // ---- stage next chunk ----
        if (chunk < NCHUNK - 1) {
            sts_chunk(smem + ((chunk + 1) & 1) * STAGE);
            if (chunk < NCHUNK - 2) ldg_chunk((chunk + 2) * KC);
        }
        __syncthreads();
    }

    // ---- epilogue: bias + relu + scale, straight from registers ----
    float scale = 1.0f;
    if (inte != nullptr) {
        const float* it = inte + task * EE;
        scale = it[0] + it[1] + it[2] + it[3];
    }

    const int r = lane >> 2;
    const int c = (lane & 3) * 2;
    #pragma unroll
    for (int mf = 0; mf < 4; ++mf) {
        const int m = m0 + wm * 64 + mf * 16 + r;
        #pragma unroll
        for (int nf = 0; nf < 4; ++nf) {
            const int n = n0 + wn * 32 + nf * 8 + c;
            float2 b2 = *reinterpret_cast<const float2*>(bt + n);
            float2 v0, v1;
            v0.x = fmaxf(acc[mf][nf][0] + b2.x, 0.0f) * scale;
            v0.y = fmaxf(acc[mf][nf][1] + b2.y, 0.0f) * scale;
            v1.x = fmaxf(acc[mf][nf][2] + b2.x, 0.0f) * scale;
            v1.y = fmaxf(acc[mf][nf][3] + b2.y, 0.0f) * scale;
            *reinterpret_cast<float2*>(
                Y + ((size_t)m * TT + task) * DD + n) = v0;
            *reinterpret_cast<float2*>(
                Y + ((size_t)(m + 8) * TT + task) * DD + n) = v1;
        }
    }
}

// ============================================================================
// Gate + combine (as round 1)
// ============================================================================
__global__ __launch_bounds__(128)
void gate_combine(const float* __restrict__ teo,  // [B, T, D]
                  const float* __restrict__ Wg,   // [D, T]
                  const float* __restrict__ bg,   // [T]
                  float* __restrict__ out)        // [B, T, D]
{
    const int b = blockIdx.x;
    __shared__ float s_teo[TT][DD];
    __shared__ float s_g[TT][TT];

    const int tid  = threadIdx.x;
    const int warp = tid >> 5;
    const int lane = tid & 31;

    const size_t base = (size_t)b * TT * DD;
    for (int idx = tid; idx < TT * DD / 4; idx += 128) {
        reinterpret_cast<float4*>(&s_teo[0][0])[idx] =
            reinterpret_cast<const float4*>(teo + base)[idx];
    }
    __syncthreads();

    float acc0 = 0.f, acc1 = 0.f, acc2 = 0.f, acc3 = 0.f;
    for (int d = lane; d < DD; d += 32) {
        float v = s_teo[warp][d];
        float4 w = reinterpret_cast<const float4*>(Wg)[d];
        acc0 = fmaf(v, w.x, acc0);
        acc1 = fmaf(v, w.y, acc1);
        acc2 = fmaf(v, w.z, acc2);
        acc3 = fmaf(v, w.w, acc3);
    }
    #pragma unroll
    for (int off = 16; off; off >>= 1) {
        acc0 += __shfl_xor_sync(0xffffffffu, acc0, off);
        acc1 += __shfl_xor_sync(0xffffffffu, acc1, off);
        acc2 += __shfl_xor_sync(0xffffffffu, acc2, off);
        acc3 += __shfl_xor_sync(0xffffffffu, acc3, off);
    }
    if (lane == 0) {
        float l0 = acc0 + bg[0], l1 = acc1 + bg[1], l2 = acc2 + bg[2], l3 = acc3 + bg[3];
        float m = fmaxf(fmaxf(l0, l1), fmaxf(l2, l3));
        float e0 = __expf(l0 - m), e1 = __expf(l1 - m), e2 = __expf(l2 - m), e3 = __expf(l3 - m);
        float inv = 1.0f / (e0 + e1 + e2 + e3);
        s_g[warp][0] = e0 * inv;
        s_g[warp][1] = e1 * inv;
        s_g[warp][2] = e2 * inv;
        s_g[warp][3] = e3 * inv;
    }
    __syncthreads();

    #pragma unroll
    for (int t = 0; t < TT; t++) {
        const float g0 = s_g[t][0], g1 = s_g[t][1], g2 = s_g[t][2], g3 = s_g[t][3];
        for (int d = tid; d < DD; d += 128) {
            float r = s_teo[t][d];
            r = fmaf(g0, s_teo[0][d], r);
            r = fmaf(g1, s_teo[1][d], r);
            r = fmaf(g2, s_teo[2][d], r);
            r = fmaf(g3, s_teo[3][d], r);
            out[base + (size_t)t * DD + d] = r;
        }
    }
}

// ============================================================================
// launch
// ============================================================================
extern "C" void kernel_launch(void* const* d_in, const int* in_sizes, int n_in,
                              void* d_out, int out_size)
{
    const float* x    = (const float*)d_in[0];
    const float* W1   = (const float*)d_in[1];
    const float* b1   = (const float*)d_in[2];
    const float* W2   = (const float*)d_in[3];
    const float* b2   = (const float*)d_in[4];
    const float* inte = (const float*)d_in[5];
    const float* Wg   = (const float*)d_in[6];
    const float* bg   = (const float*)d_in[7];
    float* out = (float*)d_out;

    cudaFuncSetAttribute(gemm_mma, cudaFuncAttributeMaxDynamicSharedMemorySize,
                         SMEM_TOTAL);

    float *t1, *teo, *h;
    cudaGetSymbolAddress((void**)&t1,  g_t1);
    cudaGetSymbolAddress((void**)&teo, g_teo);
    cudaGetSymbolAddress((void**)&h,   g_h);

    dim3 grid(DD / BN, BB / BM, TT);   // (8, 32, 4)

    const float* layer_in = x;
    for (int l = 0; l < LL; l++) {
        const float* W1l = W1 + (size_t)l * TT * DD * DD;
        const float* b1l = b1 + (size_t)l * TT * DD;
        const float* W2l = W2 + (size_t)l * TT * DD * DD;
        const float* b2l = b2 + (size_t)l * TT * DD;
        const float* il  = inte + (size_t)l * TT * EE;
        const float* Wgl = Wg + (size_t)l * DD * TT;
        const float* bgl = bg + (size_t)l * TT;

        gemm_mma<<<grid, 256, SMEM_TOTAL>>>(layer_in, W1l, b1l, nullptr, t1);
        gemm_mma<<<grid, 256, SMEM_TOTAL>>>(t1, W2l, b2l, il, teo);

        float* gate_out = (l == LL - 1) ? out : h;
        gate_combine<<<BB, 128>>>(teo, Wgl, bgl, gate_out);
        layer_in = h;
    }
}

// round 4
// speedup vs baseline: 2.9698x; 1.0658x over previous
#include <cuda_runtime.h>
#include <cuda_bf16.h>
#include <cstdint>

// Problem constants: B=4096 batch, T=4 tasks, D=1024 dim, L=2 layers, E=4.
#define BB 4096
#define TT 4
#define DD 1024
#define LL 2
#define EE 4

// GEMM tiling
#define BM 128
#define BN 128
#define KC 64
#define NCHUNK (DD / KC)   // 16

// SMEM stage: Ahi,Alo,Bhi,Blo each [128 rows][128B] SW128-swizzled = 16KB
#define OFF_AHI 0
#define OFF_ALO 16384
#define OFF_BHI 32768
#define OFF_BLO 49152
#define STAGE   65536
#define SMEM_TOTAL (2 * STAGE)   // 131072

#define SW128(x) ((x) ^ (((x) >> 3) & 0x70))

typedef __nv_bfloat16 bf16;

// -------- scratch (allocation-free: __device__ globals) --------
__device__ bf16  g_inh[TT * BB * DD], g_inl[TT * BB * DD];   // act in  [T][B][D]
__device__ bf16  g_t1h[TT * BB * DD], g_t1l[TT * BB * DD];   // stage-1 [T][B][D]
__device__ bf16  g_w1h[TT * DD * DD], g_w1l[TT * DD * DD];   // W1' [T][n][k]
__device__ bf16  g_w2h[TT * DD * DD], g_w2l[TT * DD * DD];   // W2' [T][n][k]
__device__ float g_teo[BB * TT * DD];                        // fp32 [B][T][D]

// ---------------------------------------------------------------------------
__device__ __forceinline__ uint32_t smem_u32(const void* p) {
    uint32_t a;
    asm("{ .reg .u64 t; cvta.to.shared.u64 t, %1; cvt.u32.u64 %0, t; }"
        : "=r"(a) : "l"(p));
    return a;
}

__device__ __forceinline__ void ldsm_x4(uint32_t& r0, uint32_t& r1,
                                        uint32_t& r2, uint32_t& r3,
                                        uint32_t addr) {
    asm volatile("ldmatrix.sync.aligned.m8n8.x4.shared.b16 {%0,%1,%2,%3}, [%4];"
                 : "=r"(r0), "=r"(r1), "=r"(r2), "=r"(r3) : "r"(addr));
}

__device__ __forceinline__ void mma_bf16(float* c, const uint32_t* a,
                                         const uint32_t* b) {
    asm volatile(
        "mma.sync.aligned.m16n8k16.row.col.f32.bf16.bf16.f32 "
        "{%0,%1,%2,%3}, {%4,%5,%6,%7}, {%8,%9}, {%0,%1,%2,%3};"
        : "+f"(c[0]), "+f"(c[1]), "+f"(c[2]), "+f"(c[3])
        : "r"(a[0]), "r"(a[1]), "r"(a[2]), "r"(a[3]), "r"(b[0]), "r"(b[1]));
}

#define CPA16(dst, src) \
    asm volatile("cp.async.cg.shared.global [%0], [%1], 16;" :: "r"(dst), "l"(src))
#define CPCOMMIT() asm volatile("cp.async.commit_group;" ::: "memory")
#define CPWAIT1()  asm volatile("cp.async.wait_group 1;"  ::: "memory")

// split fp32 pair -> (hi bf16x2, lo bf16x2). hi = truncation (exact in fp32).
__device__ __forceinline__ void split_pair(float v0, float v1,
                                           uint32_t& hp, uint32_t& lp) {
    uint32_t u0 = __float_as_uint(v0), u1 = __float_as_uint(v1);
    hp = (u0 >> 16) | (u1 & 0xFFFF0000u);
    float r0 = v0 - __uint_as_float(u0 & 0xFFFF0000u);
    float r1 = v1 - __uint_as_float(u1 & 0xFFFF0000u);
    __nv_bfloat162 l2 = __floats2bfloat162_rn(r0, r1);
    lp = *reinterpret_cast<uint32_t*>(&l2);
}

// ============================================================================
// prep: split x [B][T][D] fp32 -> hi/lo bf16 [T][B][D]
// ============================================================================
__global__ __launch_bounds__(256)
void split_act(const float* __restrict__ x, bf16* __restrict__ hi,
               bf16* __restrict__ lo)
{
    int p = blockIdx.x * 256 + threadIdx.x;     // pair index
    int d2 = p & (DD / 2 - 1);
    int bt = p >> 9;                            // DD/2 = 512
    int t = bt & (TT - 1);
    int b = bt >> 2;
    float2 v = reinterpret_cast<const float2*>(x)[p];
    uint32_t hp, lp;
    split_pair(v.x, v.y, hp, lp);
    size_t o = (((size_t)(t * BB + b) * DD) >> 1) + d2;
    reinterpret_cast<uint32_t*>(hi)[o] = hp;
    reinterpret_cast<uint32_t*>(lo)[o] = lp;
}

// ============================================================================
// prep: split+transpose W [T][k][n] fp32 -> hi/lo bf16 [T][n][k]
// ============================================================================
__global__ __launch_bounds__(256)
void split_w(const float* __restrict__ W, bf16* __restrict__ hi,
             bf16* __restrict__ lo)
{
    __shared__ float tile[32][33];
    const int t  = blockIdx.z;
    const int k0 = blockIdx.y * 32, n0 = blockIdx.x * 32;
    const int tx = threadIdx.x, ty = threadIdx.y;   // 32 x 8
    const float* Wt = W + (size_t)t * DD * DD;
    #pragma unroll
    for (int i = 0; i < 4; i++)
        tile[ty + i * 8][tx] = Wt[(size_t)(k0 + ty + i * 8) * DD + n0 + tx];
    __syncthreads();
    uint16_t* ht = reinterpret_cast<uint16_t*>(hi) + (size_t)t * DD * DD;
    uint16_t* lt = reinterpret_cast<uint16_t*>(lo) + (size_t)t * DD * DD;
    #pragma unroll
    for (int i = 0; i < 4; i++) {
        int n = n0 + ty + i * 8;
        float v = tile[tx][ty + i * 8];
        uint32_t u = __float_as_uint(v);
        float r = v - __uint_as_float(u & 0xFFFF0000u);
        __nv_bfloat16 lb = __float2bfloat16(r);
        size_t o = (size_t)n * DD + k0 + tx;
        ht[o] = (uint16_t)(u >> 16);
        lt[o] = *reinterpret_cast<uint16_t*>(&lb);
    }
}

// ============================================================================
// bf16-split mma.sync GEMM on pre-split operands.
// MODE 0: Y = relu(A@W + b) written as hi/lo bf16 [T][B][D]
// MODE 1: Y = relu(A@W + b) * scale written fp32 [B][T][D]
// ============================================================================
template <int MODE>
__global__ __launch_bounds__(256, 1)
void gemm_pre(const bf16* __restrict__ Ahi, const bf16* __restrict__ Alo,
              const bf16* __restrict__ Whi, const bf16* __restrict__ Wlo,
              const float* __restrict__ bias, const float* __restrict__ inte,
              void* __restrict__ Yo, bf16* __restrict__ Ylo)
{
    extern __shared__ char smem[];
    const uint32_t sbase = smem_u32(smem);
    const int tid  = threadIdx.x;
    const int warp = tid >> 5;
    const int lane = tid & 31;
    const int task = blockIdx.z;
    const int m0   = blockIdx.y * BM;
    const int n0   = blockIdx.x * BN;

    const bf16* abh = Ahi + (size_t)(task * BB + m0) * DD;
    const bf16* abl = Alo + (size_t)(task * BB + m0) * DD;
    const bf16* wbh = Whi + (size_t)(task * DD + n0) * DD;
    const bf16* wbl = Wlo + (size_t)(task * DD + n0) * DD;

    const int lrow = tid >> 3;          // 0..31 step row base (per it: +32)
    const int k16  = tid & 7;           // 16B seg within 128B row

    auto issue = [&](int c) {
        const int k0 = c * KC;
        const uint32_t stb = sbase + (c & 1) * STAGE;
        #pragma unroll
        for (int it = 0; it < 4; it++) {
            const int row = it * 32 + lrow;
            const uint32_t dsw = SW128((uint32_t)(row * 128 + k16 * 16));
            const size_t so = (size_t)row * DD + k0 + k16 * 8;
            CPA16(stb + OFF_AHI + dsw, abh + so);
            CPA16(stb + OFF_ALO + dsw, abl + so);
            CPA16(stb + OFF_BHI + dsw, wbh + so);
            CPA16(stb + OFF_BLO + dsw, wbl + so);
        }
    };

    issue(0); CPCOMMIT();
    issue(1); CPCOMMIT();

    float acc[4][4][4];
    #pragma unroll
    for (int i = 0; i < 4; ++i)
        #pragma unroll
        for (int j = 0; j < 4; ++j)
            #pragma unroll
            for (int r = 0; r < 4; ++r) acc[i][j][r] = 0.0f;

    const int wm = warp & 1;    // 64-row group
    const int wn = warp >> 1;   // 32-col group
    const int a_lrow = lane & 15;
    const int a_lcol = (lane >> 4) << 4;
    const int b_row  = ((lane >> 4) & 1) * 8 + (lane & 7);
    const int b_boff = ((lane >> 3) & 1) * 16;

    for (int c = 0; c < NCHUNK; ++c) {
        CPWAIT1();
        __syncthreads();
        const uint32_t stb = sbase + (c & 1) * STAGE;

        #pragma unroll
        for (int ks = 0; ks < 4; ++ks) {
            uint32_t ah[4][4], al[4][4], bh[4][2], bl[4][2];
            #pragma unroll
            for (int mf = 0; mf < 4; ++mf) {
                uint32_t off = SW128((uint32_t)(
                    (wm * 64 + mf * 16 + a_lrow) * 128 + ks * 32 + a_lcol));
                ldsm_x4(ah[mf][0], ah[mf][1], ah[mf][2], ah[mf][3],
                        stb + OFF_AHI + off);
                ldsm_x4(al[mf][0], al[mf][1], al[mf][2], al[mf][3],
                        stb + OFF_ALO + off);
            }
            #pragma unroll
            for (int nfp = 0; nfp < 2; ++nfp) {
                uint32_t off = SW128((uint32_t)(
                    (wn * 32 + nfp * 16 + b_row) * 128 + ks * 32 + b_boff));
                ldsm_x4(bh[2*nfp][0], bh[2*nfp][1], bh[2*nfp+1][0], bh[2*nfp+1][1],
                        stb + OFF_BHI + off);
                ldsm_x4(bl[2*nfp][0], bl[2*nfp][1], bl[2*nfp+1][0], bl[2*nfp+1][1],
                        stb + OFF_BLO + off);
            }
            #pragma unroll
            for (int mf = 0; mf < 4; ++mf)
                #pragma unroll
                for (int nf = 0; nf < 4; ++nf) {
                    mma_bf16(acc[mf][nf], ah[mf], bh[nf]);
                    mma_bf16(acc[mf][nf], ah[mf], bl[nf]);
                    mma_bf16(acc[mf][nf], al[mf], bh[nf]);
                }
        }
        __syncthreads();
        if (c + 2 < NCHUNK) issue(c + 2);
        CPCOMMIT();
    }

    // ---- epilogue ----
    const float* bt = bias + task * DD;
    const int er = lane >> 2;
    const int ec = (lane & 3) * 2;

    if constexpr (MODE == 0) {
        uint32_t* Yh32 = reinterpret_cast<uint32_t*>(Yo);
        uint32_t* Yl32 = reinterpret_cast<uint32_t*>(Ylo);
        #pragma unroll
        for (int mf = 0; mf < 4; ++mf) {
            const int m = m0 + wm * 64 + mf * 16 + er;
            #pragma unroll
            for (int nf = 0; nf < 4; ++nf) {
                const int n = n0 + wn * 32 + nf * 8 + ec;
                float2 b2 = *reinterpret_cast<const float2*>(bt + n);
                float v0 = fmaxf(acc[mf][nf][0] + b2.x, 0.0f);
                float v1 = fmaxf(acc[mf][nf][1] + b2.y, 0.0f);
                float v2 = fmaxf(acc[mf][nf][2] + b2.x, 0.0f);
                float v3 = fmaxf(acc[mf][nf][3] + b2.y, 0.0f);
                uint32_t hp, lp;
                size_t o0 = (((size_t)(task * BB + m) * DD) + n) >> 1;
                split_pair(v0, v1, hp, lp);
                Yh32[o0] = hp; Yl32[o0] = lp;
                size_t o1 = (((size_t)(task * BB + m + 8) * DD) + n) >> 1;
                split_pair(v2, v3, hp, lp);
                Yh32[o1] = hp; Yl32[o1] = lp;
            }
        }
    } else {
        float scale = 1.0f;
        if (inte != nullptr) {
            const float* it = inte + task * EE;
            scale = it[0] + it[1] + it[2] + it[3];
        }
        float* Y = reinterpret_cast<float*>(Yo);
        #pragma unroll
        for (int mf = 0; mf < 4; ++mf) {
            const int m = m0 + wm * 64 + mf * 16 + er;
            #pragma unroll
            for (int nf = 0; nf < 4; ++nf) {
                const int n = n0 + wn * 32 + nf * 8 + ec;
                float2 b2 = *reinterpret_cast<const float2*>(bt + n);
                float2 v0, v1;
                v0.x = fmaxf(acc[mf][nf][0] + b2.x, 0.0f) * scale;
                v0.y = fmaxf(acc[mf][nf][1] + b2.y, 0.0f) * scale;
                v1.x = fmaxf(acc[mf][nf][2] + b2.x, 0.0f) * scale;
                v1.y = fmaxf(acc[mf][nf][3] + b2.y, 0.0f) * scale;
                *reinterpret_cast<float2*>(Y + ((size_t)m * TT + task) * DD + n) = v0;
                *reinterpret_cast<float2*>(Y + ((size_t)(m + 8) * TT + task) * DD + n) = v1;
            }
        }
    }
}

// ============================================================================
// Gate + combine. Output: fp32 [B][T][D] (outf) OR hi/lo bf16 [T][B][D].
// ============================================================================
__global__ __launch_bounds__(128)
void gate_combine(const float* __restrict__ teo, const float* __restrict__ Wg,
                  const float* __restrict__ bg, float* __restrict__ outf,
                  bf16* __restrict__ outh, bf16* __restrict__ outl)
{
    const int b = blockIdx.x;
    __shared__ float s_teo[TT][DD];
    __shared__ float s_g[TT][TT];

    const int tid  = threadIdx.x;
    const int warp = tid >> 5;
    const int lane = tid & 31;

    const size_t base = (size_t)b * TT * DD;
    for (int idx = tid; idx < TT * DD / 4; idx += 128) {
        reinterpret_cast<float4*>(&s_teo[0][0])[idx] =
            reinterpret_cast<const float4*>(teo + base)[idx];
    }
    __syncthreads();

    float a0 = 0.f, a1 = 0.f, a2 = 0.f, a3 = 0.f;
    for (int d = lane; d < DD; d += 32) {
        float v = s_teo[warp][d];
        float4 w = reinterpret_cast<const float4*>(Wg)[d];
        a0 = fmaf(v, w.x, a0);
        a1 = fmaf(v, w.y, a1);
        a2 = fmaf(v, w.z, a2);
        a3 = fmaf(v, w.w, a3);
    }
    #pragma unroll
    for (int off = 16; off; off >>= 1) {
        a0 += __shfl_xor_sync(0xffffffffu, a0, off);
        a1 += __shfl_xor_sync(0xffffffffu, a1, off);
        a2 += __shfl_xor_sync(0xffffffffu, a2, off);
        a3 += __shfl_xor_sync(0xffffffffu, a3, off);
    }
    if (lane == 0) {
        float l0 = a0 + bg[0], l1 = a1 + bg[1], l2 = a2 + bg[2], l3 = a3 + bg[3];
        float m = fmaxf(fmaxf(l0, l1), fmaxf(l2, l3));
        float e0 = __expf(l0 - m), e1 = __expf(l1 - m);
        float e2 = __expf(l2 - m), e3 = __expf(l3 - m);
        float inv = 1.0f / (e0 + e1 + e2 + e3);
        s_g[warp][0] = e0 * inv;
        s_g[warp][1] = e1 * inv;
        s_g[warp][2] = e2 * inv;
        s_g[warp][3] = e3 * inv;
    }
    __syncthreads();

    #pragma unroll
    for (int t = 0; t < TT; t++) {
        const float g0 = s_g[t][0], g1 = s_g[t][1], g2 = s_g[t][2], g3 = s_g[t][3];
        for (int d2 = tid; d2 < DD / 2; d2 += 128) {
            const int d = d2 * 2;
            float r0 = s_teo[t][d], r1 = s_teo[t][d + 1];
            r0 = fmaf(g0, s_teo[0][d], r0);     r1 = fmaf(g0, s_teo[0][d+1], r1);
            r0 = fmaf(g1, s_teo[1][d], r0);     r1 = fmaf(g1, s_teo[1][d+1], r1);
            r0 = fmaf(g2, s_teo[2][d], r0);     r1 = fmaf(g2, s_teo[2][d+1], r1);
            r0 = fmaf(g3, s_teo[3][d], r0);     r1 = fmaf(g3, s_teo[3][d+1], r1);
            if (outf != nullptr) {
                float2 v; v.x = r0; v.y = r1;
                *reinterpret_cast<float2*>(outf + base + (size_t)t * DD + d) = v;
            } else {
                uint32_t hp, lp;
                split_pair(r0, r1, hp, lp);
                size_t o = (((size_t)(t * BB + b) * DD) + d) >> 1;
                reinterpret_cast<uint32_t*>(outh)[o] = hp;
                reinterpret_cast<uint32_t*>(outl)[o] = lp;
            }
        }
    }
}

// ============================================================================
// launch
// ============================================================================
extern "C" void kernel_launch(void* const* d_in, const int* in_sizes, int n_in,
                              void* d_out, int out_size)
{
    const float* x    = (const float*)d_in[0];
    const float* W1   = (const float*)d_in[1];
    const float* b1   = (const float*)d_in[2];
    const float* W2   = (const float*)d_in[3];
    const float* b2   = (const float*)d_in[4];
    const float* inte = (const float*)d_in[5];
    const float* Wg   = (const float*)d_in[6];
    const float* bg   = (const float*)d_in[7];
    float* out = (float*)d_out;

    cudaFuncSetAttribute(gemm_pre<0>, cudaFuncAttributeMaxDynamicSharedMemorySize,
                         SMEM_TOTAL);
    cudaFuncSetAttribute(gemm_pre<1>, cudaFuncAttributeMaxDynamicSharedMemorySize,
                         SMEM_TOTAL);

    bf16 *inh, *inl, *t1h, *t1l, *w1h, *w1l, *w2h, *w2l;
    float* teo;
    cudaGetSymbolAddress((void**)&inh, g_inh);
    cudaGetSymbolAddress((void**)&inl, g_inl);
    cudaGetSymbolAddress((void**)&t1h, g_t1h);
    cudaGetSymbolAddress((void**)&t1l, g_t1l);
    cudaGetSymbolAddress((void**)&w1h, g_w1h);
    cudaGetSymbolAddress((void**)&w1l, g_w1l);
    cudaGetSymbolAddress((void**)&w2h, g_w2h);
    cudaGetSymbolAddress((void**)&w2l, g_w2l);
    cudaGetSymbolAddress((void**)&teo, g_teo);

    // split input activations
    split_act<<<(BB * TT * DD / 2) / 256, 256>>>(x, inh, inl);

    dim3 ggrid(DD / BN, BB / BM, TT);             // (8, 32, 4)
    dim3 wgrid(DD / 32, DD / 32, TT);             // (32, 32, 4)
    dim3 wblk(32, 8);

    for (int l = 0; l < LL; l++) {
        const float* W1l = W1 + (size_t)l * TT * DD * DD;
        const float* b1l = b1 + (size_t)l * TT * DD;
        const float* W2l = W2 + (size_t)l * TT * DD * DD;
        const float* b2l = b2 + (size_t)l * TT * DD;
        const float* il  = inte + (size_t)l * TT * EE;
        const float* Wgl = Wg + (size_t)l * DD * TT;
        const float* bgl = bg + (size_t)l * TT;

        split_w<<<wgrid, wblk>>>(W1l, w1h, w1l);
        split_w<<<wgrid, wblk>>>(W2l, w2h, w2l);

        gemm_pre<0><<<ggrid, 256, SMEM_TOTAL>>>(inh, inl, w1h, w1l, b1l,
                                                nullptr, t1h, t1l);
        gemm_pre<1><<<ggrid, 256, SMEM_TOTAL>>>(t1h, t1l, w2h, w2l, b2l,
                                                il, teo, nullptr);

        if (l == LL - 1)
            gate_combine<<<BB, 128>>>(teo, Wgl, bgl, out, nullptr, nullptr);
        else
            gate_combine<<<BB, 128>>>(teo, Wgl, bgl, nullptr, inh, inl);
    }
}

// round 5
// speedup vs baseline: 4.0669x; 1.3694x over previous
#include <cuda_runtime.h>
#include <cuda_fp16.h>
#include <cstdint>

// Problem constants: B=4096 batch, T=4 tasks, D=1024 dim, L=2 layers, E=4.
#define BB 4096
#define TT 4
#define DD 1024
#define LL 2
#define EE 4

// GEMM tiling
#define BM 128
#define BN 128
#define KC 64
#define NCHUNK (DD / KC)   // 16
#define NSTAGE 4

// SMEM stage: Ah, Wh, Wl each [128 rows][128B] SW128-swizzled = 16KB
#define OFF_A  0
#define OFF_WH 16384
#define OFF_WL 32768
#define STAGE  49152
#define SMEM_TOTAL (NSTAGE * STAGE)   // 196608

#define SW128(x) ((x) ^ (((x) >> 3) & 0x70))

typedef __half fp16;

// -------- scratch (allocation-free: __device__ globals) --------
__device__ fp16  g_in [TT * BB * DD];                        // act in  [T][B][D]
__device__ fp16  g_t1 [TT * BB * DD];                        // stage-1 [T][B][D]
__device__ fp16  g_w1h[TT * DD * DD], g_w1l[TT * DD * DD];   // W1' [T][n][k]
__device__ fp16  g_w2h[TT * DD * DD], g_w2l[TT * DD * DD];   // W2' [T][n][k]
__device__ float g_teo[BB * TT * DD];                        // fp32 [B][T][D]

// ---------------------------------------------------------------------------
__device__ __forceinline__ uint32_t smem_u32(const void* p) {
    uint32_t a;
    asm("{ .reg .u64 t; cvta.to.shared.u64 t, %1; cvt.u32.u64 %0, t; }"
        : "=r"(a) : "l"(p));
    return a;
}

__device__ __forceinline__ void ldsm_x4(uint32_t& r0, uint32_t& r1,
                                        uint32_t& r2, uint32_t& r3,
                                        uint32_t addr) {
    asm volatile("ldmatrix.sync.aligned.m8n8.x4.shared.b16 {%0,%1,%2,%3}, [%4];"
                 : "=r"(r0), "=r"(r1), "=r"(r2), "=r"(r3) : "r"(addr));
}

__device__ __forceinline__ void mma_fp16(float* c, const uint32_t* a,
                                         const uint32_t* b) {
    asm volatile(
        "mma.sync.aligned.m16n8k16.row.col.f32.f16.f16.f32 "
        "{%0,%1,%2,%3}, {%4,%5,%6,%7}, {%8,%9}, {%0,%1,%2,%3};"
        : "+f"(c[0]), "+f"(c[1]), "+f"(c[2]), "+f"(c[3])
        : "r"(a[0]), "r"(a[1]), "r"(a[2]), "r"(a[3]), "r"(b[0]), "r"(b[1]));
}

#define CPA16(dst, src) \
    asm volatile("cp.async.cg.shared.global [%0], [%1], 16;" :: "r"(dst), "l"(src))
#define CPCOMMIT() asm volatile("cp.async.commit_group;" ::: "memory")
#define CPWAIT2()  asm volatile("cp.async.wait_group 2;"  ::: "memory")

__device__ __forceinline__ uint32_t pack_h2(float v0, float v1) {
    __half2 h = __floats2half2_rn(v0, v1);
    return *reinterpret_cast<uint32_t*>(&h);
}

// ============================================================================
// prep: x [B][T][D] fp32 -> fp16 [T][B][D] (single, RN)
// ============================================================================
__global__ __launch_bounds__(256)
void split_act(const float* __restrict__ x, fp16* __restrict__ a)
{
    int p = blockIdx.x * 256 + threadIdx.x;     // pair index
    int d2 = p & (DD / 2 - 1);
    int bt = p >> 9;                            // DD/2 = 512
    int t = bt & (TT - 1);
    int b = bt >> 2;
    float2 v = reinterpret_cast<const float2*>(x)[p];
    size_t o = (((size_t)(t * BB + b) * DD) >> 1) + d2;
    reinterpret_cast<uint32_t*>(a)[o] = pack_h2(v.x, v.y);
}

// ============================================================================
// prep: split+transpose W [T][k][n] fp32 -> fp16 hi/lo [T][n][k]
// ============================================================================
__global__ __launch_bounds__(256)
void split_w(const float* __restrict__ W, fp16* __restrict__ hi,
             fp16* __restrict__ lo)
{
    __shared__ float tile[32][33];
    const int t  = blockIdx.z;
    const int k0 = blockIdx.y * 32, n0 = blockIdx.x * 32;
    const int tx = threadIdx.x, ty = threadIdx.y;   // 32 x 8
    const float* Wt = W + (size_t)t * DD * DD;
    #pragma unroll
    for (int i = 0; i < 4; i++)
        tile[ty + i * 8][tx] = Wt[(size_t)(k0 + ty + i * 8) * DD + n0 + tx];
    __syncthreads();
    uint16_t* ht = reinterpret_cast<uint16_t*>(hi) + (size_t)t * DD * DD;
    uint16_t* lt = reinterpret_cast<uint16_t*>(lo) + (size_t)t * DD * DD;
    #pragma unroll
    for (int i = 0; i < 4; i++) {
        int n = n0 + ty + i * 8;
        float v = tile[tx][ty + i * 8];
        __half h = __float2half_rn(v);
        __half l = __float2half_rn(v - __half2float(h));
        size_t o = (size_t)n * DD + k0 + tx;
        ht[o] = *reinterpret_cast<uint16_t*>(&h);
        lt[o] = *reinterpret_cast<uint16_t*>(&l);
    }
}

// ============================================================================
// fp16-split mma.sync GEMM:  acc = A @ (Wh + Wl)
// MODE 0: Y = relu(acc + b)            -> fp16 [T][B][D]
// MODE 1: Y = relu(acc + b) * scale    -> fp32 [B][T][D]
// ============================================================================
template <int MODE>
__global__ __launch_bounds__(256, 1)
void gemm_pre(const fp16* __restrict__ Ain,
              const fp16* __restrict__ Whi, const fp16* __restrict__ Wlo,
              const float* __restrict__ bias, const float* __restrict__ inte,
              void* __restrict__ Yo)
{
    extern __shared__ char smem[];
    const uint32_t sbase = smem_u32(smem);
    const int tid  = threadIdx.x;
    const int warp = tid >> 5;
    const int lane = tid & 31;
    const int task = blockIdx.z;
    const int m0   = blockIdx.y * BM;
    const int n0   = blockIdx.x * BN;

    const fp16* ab  = Ain + (size_t)(task * BB + m0) * DD;
    const fp16* wbh = Whi + (size_t)(task * DD + n0) * DD;
    const fp16* wbl = Wlo + (size_t)(task * DD + n0) * DD;

    const int lrow = tid >> 3;          // 0..31 (per it: +32)
    const int k16  = tid & 7;           // 16B seg within 128B row

    auto issue = [&](int c) {
        const int k0 = c * KC;
        const uint32_t stb = sbase + (c & (NSTAGE - 1)) * STAGE;
        #pragma unroll
        for (int it = 0; it < 4; it++) {
            const int row = it * 32 + lrow;
            const uint32_t dsw = SW128((uint32_t)(row * 128 + k16 * 16));
            const size_t so = (size_t)row * DD + k0 + k16 * 8;
            CPA16(stb + OFF_A  + dsw, ab  + so);
            CPA16(stb + OFF_WH + dsw, wbh + so);
            CPA16(stb + OFF_WL + dsw, wbl + so);
        }
    };

    issue(0); CPCOMMIT();
    issue(1); CPCOMMIT();
    issue(2); CPCOMMIT();

    float acc[4][4][4];
    #pragma unroll
    for (int i = 0; i < 4; ++i)
        #pragma unroll
        for (int j = 0; j < 4; ++j)
            #pragma unroll
            for (int r = 0; r < 4; ++r) acc[i][j][r] = 0.0f;

    const int wm = warp & 1;    // 64-row group
    const int wn = warp >> 1;   // 32-col group
    const int a_lrow = lane & 15;
    const int a_lcol = (lane >> 4) << 4;
    const int b_row  = ((lane >> 4) & 1) * 8 + (lane & 7);
    const int b_boff = ((lane >> 3) & 1) * 16;

    for (int c = 0; c < NCHUNK; ++c) {
        CPWAIT2();
        __syncthreads();
        // prefetch stage c+3 (its buffer was last read in chunk c-1; the
        // barrier above guarantees all warps are past those reads)
        if (c + 3 < NCHUNK) issue(c + 3);
        CPCOMMIT();

        const uint32_t stb = sbase + (c & (NSTAGE - 1)) * STAGE;

        #pragma unroll
        for (int ks = 0; ks < 4; ++ks) {
            uint32_t ah[4][4], bh[4][2], bl[4][2];
            #pragma unroll
            for (int mf = 0; mf < 4; ++mf) {
                uint32_t off = SW128((uint32_t)(
                    (wm * 64 + mf * 16 + a_lrow) * 128 + ks * 32 + a_lcol));
                ldsm_x4(ah[mf][0], ah[mf][1], ah[mf][2], ah[mf][3],
                        stb + OFF_A + off);
            }
            #pragma unroll
            for (int nfp = 0; nfp < 2; ++nfp) {
                uint32_t off = SW128((uint32_t)(
                    (wn * 32 + nfp * 16 + b_row) * 128 + ks * 32 + b_boff));
                ldsm_x4(bh[2*nfp][0], bh[2*nfp][1], bh[2*nfp+1][0], bh[2*nfp+1][1],
                        stb + OFF_WH + off);
                ldsm_x4(bl[2*nfp][0], bl[2*nfp][1], bl[2*nfp+1][0], bl[2*nfp+1][1],
                        stb + OFF_WL + off);
            }
            #pragma unroll
            for (int mf = 0; mf < 4; ++mf)
                #pragma unroll
                for (int nf = 0; nf < 4; ++nf) {
                    mma_fp16(acc[mf][nf], ah[mf], bh[nf]);
                    mma_fp16(acc[mf][nf], ah[mf], bl[nf]);
                }
        }
        __syncthreads();
    }

    // ---- epilogue ----
    const float* bt = bias + task * DD;
    const int er = lane >> 2;
    const int ec = (lane & 3) * 2;

    if constexpr (MODE == 0) {
        uint32_t* Y32 = reinterpret_cast<uint32_t*>(Yo);
        #pragma unroll
        for (int mf = 0; mf < 4; ++mf) {
            const int m = m0 + wm * 64 + mf * 16 + er;
            #pragma unroll
            for (int nf = 0; nf < 4; ++nf) {
                const int n = n0 + wn * 32 + nf * 8 + ec;
                float2 b2 = *reinterpret_cast<const float2*>(bt + n);
                float v0 = fmaxf(acc[mf][nf][0] + b2.x, 0.0f);
                float v1 = fmaxf(acc[mf][nf][1] + b2.y, 0.0f);
                float v2 = fmaxf(acc[mf][nf][2] + b2.x, 0.0f);
                float v3 = fmaxf(acc[mf][nf][3] + b2.y, 0.0f);
                Y32[(((size_t)(task * BB + m)     * DD) + n) >> 1] = pack_h2(v0, v1);
                Y32[(((size_t)(task * BB + m + 8) * DD) + n) >> 1] = pack_h2(v2, v3);
            }
        }
    } else {
        float scale = 1.0f;
        if (inte != nullptr) {
            const float* it = inte + task * EE;
            scale = it[0] + it[1] + it[2] + it[3];
        }
        float* Y = reinterpret_cast<float*>(Yo);
        #pragma unroll
        for (int mf = 0; mf < 4; ++mf) {
            const int m = m0 + wm * 64 + mf * 16 + er;
            #pragma unroll
            for (int nf = 0; nf < 4; ++nf) {
                const int n = n0 + wn * 32 + nf * 8 + ec;
                float2 b2 = *reinterpret_cast<const float2*>(bt + n);
                float2 v0, v1;
                v0.x = fmaxf(acc[mf][nf][0] + b2.x, 0.0f) * scale;
                v0.y = fmaxf(acc[mf][nf][1] + b2.y, 0.0f) * scale;
                v1.x = fmaxf(acc[mf][nf][2] + b2.x, 0.0f) * scale;
                v1.y = fmaxf(acc[mf][nf][3] + b2.y, 0.0f) * scale;
                *reinterpret_cast<float2*>(Y + ((size_t)m * TT + task) * DD + n) = v0;
                *reinterpret_cast<float2*>(Y + ((size_t)(m + 8) * TT + task) * DD + n) = v1;
            }
        }
    }
}

// ============================================================================
// Gate + combine. Output: fp32 [B][T][D] (outf) OR fp16 [T][B][D] (outh).
// ============================================================================
__global__ __launch_bounds__(128)
void gate_combine(const float* __restrict__ teo, const float* __restrict__ Wg,
                  const float* __restrict__ bg, float* __restrict__ outf,
                  fp16* __restrict__ outh)
{
    const int b = blockIdx.x;
    __shared__ float s_teo[TT][DD];
    __shared__ float s_g[TT][TT];

    const int tid  = threadIdx.x;
    const int warp = tid >> 5;
    const int lane = tid & 31;

    const size_t base = (size_t)b * TT * DD;
    for (int idx = tid; idx < TT * DD / 4; idx += 128) {
        reinterpret_cast<float4*>(&s_teo[0][0])[idx] =
            reinterpret_cast<const float4*>(teo + base)[idx];
    }
    __syncthreads();

    float a0 = 0.f, a1 = 0.f, a2 = 0.f, a3 = 0.f;
    for (int d = lane; d < DD; d += 32) {
        float v = s_teo[warp][d];
        float4 w = reinterpret_cast<const float4*>(Wg)[d];
        a0 = fmaf(v, w.x, a0);
        a1 = fmaf(v, w.y, a1);
        a2 = fmaf(v, w.z, a2);
        a3 = fmaf(v, w.w, a3);
    }
    #pragma unroll
    for (int off = 16; off; off >>= 1) {
        a0 += __shfl_xor_sync(0xffffffffu, a0, off);
        a1 += __shfl_xor_sync(0xffffffffu, a1, off);
        a2 += __shfl_xor_sync(0xffffffffu, a2, off);
        a3 += __shfl_xor_sync(0xffffffffu, a3, off);
    }
    if (lane == 0) {
        float l0 = a0 + bg[0], l1 = a1 + bg[1], l2 = a2 + bg[2], l3 = a3 + bg[3];
        float m = fmaxf(fmaxf(l0, l1), fmaxf(l2, l3));
        float e0 = __expf(l0 - m), e1 = __expf(l1 - m);
        float e2 = __expf(l2 - m), e3 = __expf(l3 - m);
        float inv = 1.0f / (e0 + e1 + e2 + e3);
        s_g[warp][0] = e0 * inv;
        s_g[warp][1] = e1 * inv;
        s_g[warp][2] = e2 * inv;
        s_g[warp][3] = e3 * inv;
    }
    __syncthreads();

    #pragma unroll
    for (int t = 0; t < TT; t++) {
        const float g0 = s_g[t][0], g1 = s_g[t][1], g2 = s_g[t][2], g3 = s_g[t][3];
        for (int d2 = tid; d2 < DD / 2; d2 += 128) {
            const int d = d2 * 2;
            float r0 = s_teo[t][d], r1 = s_teo[t][d + 1];
            r0 = fmaf(g0, s_teo[0][d], r0);     r1 = fmaf(g0, s_teo[0][d+1], r1);
            r0 = fmaf(g1, s_teo[1][d], r0);     r1 = fmaf(g1, s_teo[1][d+1], r1);
            r0 = fmaf(g2, s_teo[2][d], r0);     r1 = fmaf(g2, s_teo[2][d+1], r1);
            r0 = fmaf(g3, s_teo[3][d], r0);     r1 = fmaf(g3, s_teo[3][d+1], r1);
            if (outf != nullptr) {
                float2 v; v.x = r0; v.y = r1;
                *reinterpret_cast<float2*>(outf + base + (size_t)t * DD + d) = v;
            } else {
                size_t o = (((size_t)(t * BB + b) * DD) + d) >> 1;
                reinterpret_cast<uint32_t*>(outh)[o] = pack_h2(r0, r1);
            }
        }
    }
}

// ============================================================================
// launch
// ============================================================================
extern "C" void kernel_launch(void* const* d_in, const int* in_sizes, int n_in,
                              void* d_out, int out_size)
{
    const float* x    = (const float*)d_in[0];
    const float* W1   = (const float*)d_in[1];
    const float* b1   = (const float*)d_in[2];
    const float* W2   = (const float*)d_in[3];
    const float* b2   = (const float*)d_in[4];
    const float* inte = (const float*)d_in[5];
    const float* Wg   = (const float*)d_in[6];
    const float* bg   = (const float*)d_in[7];
    float* out = (float*)d_out;

    cudaFuncSetAttribute(gemm_pre<0>, cudaFuncAttributeMaxDynamicSharedMemorySize,
                         SMEM_TOTAL);
    cudaFuncSetAttribute(gemm_pre<1>, cudaFuncAttributeMaxDynamicSharedMemorySize,
                         SMEM_TOTAL);

    fp16 *ain, *t1, *w1h, *w1l, *w2h, *w2l;
    float* teo;
    cudaGetSymbolAddress((void**)&ain, g_in);
    cudaGetSymbolAddress((void**)&t1,  g_t1);
    cudaGetSymbolAddress((void**)&w1h, g_w1h);
    cudaGetSymbolAddress((void**)&w1l, g_w1l);
    cudaGetSymbolAddress((void**)&w2h, g_w2h);
    cudaGetSymbolAddress((void**)&w2l, g_w2l);
    cudaGetSymbolAddress((void**)&teo, g_teo);

    split_act<<<(BB * TT * DD / 2) / 256, 256>>>(x, ain);

    dim3 ggrid(DD / BN, BB / BM, TT);             // (8, 32, 4)
    dim3 wgrid(DD / 32, DD / 32, TT);             // (32, 32, 4)
    dim3 wblk(32, 8);

    for (int l = 0; l < LL; l++) {
        const float* W1l = W1 + (size_t)l * TT * DD * DD;
        const float* b1l = b1 + (size_t)l * TT * DD;
        const float* W2l = W2 + (size_t)l * TT * DD * DD;
        const float* b2l = b2 + (size_t)l * TT * DD;
        const float* il  = inte + (size_t)l * TT * EE;
        const float* Wgl = Wg + (size_t)l * DD * TT;
        const float* bgl = bg + (size_t)l * TT;

        split_w<<<wgrid, wblk>>>(W1l, w1h, w1l);
        split_w<<<wgrid, wblk>>>(W2l, w2h, w2l);

        gemm_pre<0><<<ggrid, 256, SMEM_TOTAL>>>(ain, w1h, w1l, b1l, nullptr, t1);
        gemm_pre<1><<<ggrid, 256, SMEM_TOTAL>>>(t1, w2h, w2l, b2l, il, teo);

        if (l == LL - 1)
            gate_combine<<<BB, 128>>>(teo, Wgl, bgl, out, nullptr);
        else
            gate_combine<<<BB, 128>>>(teo, Wgl, bgl, nullptr, ain);
    }
}

// round 6
// speedup vs baseline: 4.1644x; 1.0240x over previous
#include <cuda_runtime.h>
#include <cuda_fp16.h>
#include <cstdint>

// Problem constants: B=4096 batch, T=4 tasks, D=1024 dim, L=2 layers, E=4.
#define BB 4096
#define TT 4
#define DD 1024
#define LL 2
#define EE 4

// GEMM tiling
#define BM 128
#define BN 128
#define KC 64
#define NCHUNK (DD / KC)   // 16
#define NSTAGE 4

// SMEM stage: Ah, Wh, Wl each [128 rows][128B] SW128-swizzled = 16KB
#define OFF_A  0
#define OFF_WH 16384
#define OFF_WL 32768
#define STAGE  49152
#define SMEM_TOTAL (NSTAGE * STAGE)   // 196608

#define SW128(x) ((x) ^ (((x) >> 3) & 0x70))

typedef __half fp16;

// -------- scratch (allocation-free: __device__ globals) --------
__device__ fp16  g_in [TT * BB * DD];                        // act in  [T][B][D]
__device__ fp16  g_t1 [TT * BB * DD];                        // stage-1 [T][B][D]
__device__ fp16  g_w1h[TT * DD * DD], g_w1l[TT * DD * DD];   // W1' [T][n][k]
__device__ fp16  g_w2h[TT * DD * DD], g_w2l[TT * DD * DD];   // W2' [T][n][k]
__device__ float g_teo[BB * TT * DD];                        // fp32 [B][T][D]

// ---------------------------------------------------------------------------
__device__ __forceinline__ uint32_t smem_u32(const void* p) {
    uint32_t a;
    asm("{ .reg .u64 t; cvta.to.shared.u64 t, %1; cvt.u32.u64 %0, t; }"
        : "=r"(a) : "l"(p));
    return a;
}

__device__ __forceinline__ void ldsm_x4(uint32_t& r0, uint32_t& r1,
                                        uint32_t& r2, uint32_t& r3,
                                        uint32_t addr) {
    asm volatile("ldmatrix.sync.aligned.m8n8.x4.shared.b16 {%0,%1,%2,%3}, [%4];"
                 : "=r"(r0), "=r"(r1), "=r"(r2), "=r"(r3) : "r"(addr));
}

__device__ __forceinline__ void mma_fp16(float* c, const uint32_t* a,
                                         const uint32_t* b) {
    asm volatile(
        "mma.sync.aligned.m16n8k16.row.col.f32.f16.f16.f32 "
        "{%0,%1,%2,%3}, {%4,%5,%6,%7}, {%8,%9}, {%0,%1,%2,%3};"
        : "+f"(c[0]), "+f"(c[1]), "+f"(c[2]), "+f"(c[3])
        : "r"(a[0]), "r"(a[1]), "r"(a[2]), "r"(a[3]), "r"(b[0]), "r"(b[1]));
}

#define CPA16(dst, src) \
    asm volatile("cp.async.cg.shared.global [%0], [%1], 16;" :: "r"(dst), "l"(src))
#define CPCOMMIT() asm volatile("cp.async.commit_group;" ::: "memory")
#define CPWAIT2()  asm volatile("cp.async.wait_group 2;"  ::: "memory")

__device__ __forceinline__ uint32_t pack_h2(float v0, float v1) {
    __half2 h = __floats2half2_rn(v0, v1);
    return *reinterpret_cast<uint32_t*>(&h);
}

// ============================================================================
// prep: x [B][T][D] fp32 -> fp16 [T][B][D] (single, RN)
// ============================================================================
__global__ __launch_bounds__(256)
void split_act(const float* __restrict__ x, fp16* __restrict__ a)
{
    int p = blockIdx.x * 256 + threadIdx.x;     // pair index
    int d2 = p & (DD / 2 - 1);
    int bt = p >> 9;                            // DD/2 = 512
    int t = bt & (TT - 1);
    int b = bt >> 2;
    float2 v = reinterpret_cast<const float2*>(x)[p];
    size_t o = (((size_t)(t * BB + b) * DD) >> 1) + d2;
    reinterpret_cast<uint32_t*>(a)[o] = pack_h2(v.x, v.y);
}

// ============================================================================
// prep: split+transpose W [k][n] fp32 -> fp16 hi/lo [n][k]
// grid.z = 2*TT: z<TT -> W1/task z ; z>=TT -> W2/task z-TT
// ============================================================================
__global__ __launch_bounds__(256)
void split_w(const float* __restrict__ W1, const float* __restrict__ W2,
             fp16* __restrict__ hi1, fp16* __restrict__ lo1,
             fp16* __restrict__ hi2, fp16* __restrict__ lo2)
{
    __shared__ float tile[32][33];
    const int z  = blockIdx.z;
    const int t  = (z < TT) ? z : z - TT;
    const float* Wt = ((z < TT) ? W1 : W2) + (size_t)t * DD * DD;
    uint16_t* ht = reinterpret_cast<uint16_t*>((z < TT) ? hi1 : hi2) + (size_t)t * DD * DD;
    uint16_t* lt = reinterpret_cast<uint16_t*>((z < TT) ? lo1 : lo2) + (size_t)t * DD * DD;

    const int k0 = blockIdx.y * 32, n0 = blockIdx.x * 32;
    const int tx = threadIdx.x, ty = threadIdx.y;   // 32 x 8
    #pragma unroll
    for (int i = 0; i < 4; i++)
        tile[ty + i * 8][tx] = Wt[(size_t)(k0 + ty + i * 8) * DD + n0 + tx];
    __syncthreads();
    #pragma unroll
    for (int i = 0; i < 4; i++) {
        int n = n0 + ty + i * 8;
        float v = tile[tx][ty + i * 8];
        __half h = __float2half_rn(v);
        __half l = __float2half_rn(v - __half2float(h));
        size_t o = (size_t)n * DD + k0 + tx;
        ht[o] = *reinterpret_cast<uint16_t*>(&h);
        lt[o] = *reinterpret_cast<uint16_t*>(&l);
    }
}

// ============================================================================
// fp16-split mma.sync GEMM:  acc = A @ (Wh + Wl)
// MODE 0: Y = relu(acc + b)            -> fp16 [T][B][D]
// MODE 1: Y = relu(acc + b) * scale    -> fp32 [B][T][D]
// ============================================================================
template <int MODE>
__global__ __launch_bounds__(256, 1)
void gemm_pre(const fp16* __restrict__ Ain,
              const fp16* __restrict__ Whi, const fp16* __restrict__ Wlo,
              const float* __restrict__ bias, const float* __restrict__ inte,
              void* __restrict__ Yo)
{
    extern __shared__ char smem[];
    const uint32_t sbase = smem_u32(smem);
    const int tid  = threadIdx.x;
    const int warp = tid >> 5;
    const int lane = tid & 31;
    const int task = blockIdx.z;
    const int m0   = blockIdx.y * BM;
    const int n0   = blockIdx.x * BN;

    const fp16* ab  = Ain + (size_t)(task * BB + m0) * DD;
    const fp16* wbh = Whi + (size_t)(task * DD + n0) * DD;
    const fp16* wbl = Wlo + (size_t)(task * DD + n0) * DD;

    const int lrow = tid >> 3;          // 0..31 (per it: +32)
    const int k16  = tid & 7;           // 16B seg within 128B row

    auto issue = [&](int c) {
        const int k0 = c * KC;
        const uint32_t stb = sbase + (c & (NSTAGE - 1)) * STAGE;
        #pragma unroll
        for (int it = 0; it < 4; it++) {
            const int row = it * 32 + lrow;
            const uint32_t dsw = SW128((uint32_t)(row * 128 + k16 * 16));
            const size_t so = (size_t)row * DD + k0 + k16 * 8;
            CPA16(stb + OFF_A  + dsw, ab  + so);
            CPA16(stb + OFF_WH + dsw, wbh + so);
            CPA16(stb + OFF_WL + dsw, wbl + so);
        }
    };

    issue(0); CPCOMMIT();
    issue(1); CPCOMMIT();
    issue(2); CPCOMMIT();

    float acc[4][4][4];
    #pragma unroll
    for (int i = 0; i < 4; ++i)
        #pragma unroll
        for (int j = 0; j < 4; ++j)
            #pragma unroll
            for (int r = 0; r < 4; ++r) acc[i][j][r] = 0.0f;

    const int wm = warp & 1;    // 64-row group
    const int wn = warp >> 1;   // 32-col group
    const int a_lrow = lane & 15;
    const int a_lcol = (lane >> 4) << 4;
    const int b_row  = ((lane >> 4) & 1) * 8 + (lane & 7);
    const int b_boff = ((lane >> 3) & 1) * 16;

    // double-buffered fragments (register pipeline over ks)
    uint32_t ah[2][4][4], bh[2][4][2], bl[2][4][2];

    auto load_frags = [&](uint32_t stb, int ks, int pb) {
        #pragma unroll
        for (int mf = 0; mf < 4; ++mf) {
            uint32_t off = SW128((uint32_t)(
                (wm * 64 + mf * 16 + a_lrow) * 128 + ks * 32 + a_lcol));
            ldsm_x4(ah[pb][mf][0], ah[pb][mf][1], ah[pb][mf][2], ah[pb][mf][3],
                    stb + OFF_A + off);
        }
        #pragma unroll
        for (int nfp = 0; nfp < 2; ++nfp) {
            uint32_t off = SW128((uint32_t)(
                (wn * 32 + nfp * 16 + b_row) * 128 + ks * 32 + b_boff));
            ldsm_x4(bh[pb][2*nfp][0], bh[pb][2*nfp][1],
                    bh[pb][2*nfp+1][0], bh[pb][2*nfp+1][1],
                    stb + OFF_WH + off);
            ldsm_x4(bl[pb][2*nfp][0], bl[pb][2*nfp][1],
                    bl[pb][2*nfp+1][0], bl[pb][2*nfp+1][1],
                    stb + OFF_WL + off);
        }
    };

    for (int c = 0; c < NCHUNK; ++c) {
        CPWAIT2();
        __syncthreads();
        // prefetch stage c+3 (its buffer was last read in chunk c-1; every
        // warp passed this barrier, so all c-1 reads are complete)
        if (c + 3 < NCHUNK) issue(c + 3);
        CPCOMMIT();

        const uint32_t stb = sbase + (c & (NSTAGE - 1)) * STAGE;

        load_frags(stb, 0, 0);
        #pragma unroll
        for (int ks = 0; ks < 4; ++ks) {
            const int cur = ks & 1;
            if (ks < 3) load_frags(stb, ks + 1, cur ^ 1);   // LSU ahead of tensor
            #pragma unroll
            for (int mf = 0; mf < 4; ++mf)
                #pragma unroll
                for (int nf = 0; nf < 4; ++nf) {
                    mma_fp16(acc[mf][nf], ah[cur][mf], bh[cur][nf]);
                    mma_fp16(acc[mf][nf], ah[cur][mf], bl[cur][nf]);
                }
        }
        // NOTE: no trailing __syncthreads — next iteration's barrier provides
        // the read/write separation.
    }

    // ---- epilogue ----
    const float* bt = bias + task * DD;
    const int er = lane >> 2;
    const int ec = (lane & 3) * 2;

    if constexpr (MODE == 0) {
        uint32_t* Y32 = reinterpret_cast<uint32_t*>(Yo);
        #pragma unroll
        for (int mf = 0; mf < 4; ++mf) {
            const int m = m0 + wm * 64 + mf * 16 + er;
            #pragma unroll
            for (int nf = 0; nf < 4; ++nf) {
                const int n = n0 + wn * 32 + nf * 8 + ec;
                float2 b2 = *reinterpret_cast<const float2*>(bt + n);
                float v0 = fmaxf(acc[mf][nf][0] + b2.x, 0.0f);
                float v1 = fmaxf(acc[mf][nf][1] + b2.y, 0.0f);
                float v2 = fmaxf(acc[mf][nf][2] + b2.x, 0.0f);
                float v3 = fmaxf(acc[mf][nf][3] + b2.y, 0.0f);
                Y32[(((size_t)(task * BB + m)     * DD) + n) >> 1] = pack_h2(v0, v1);
                Y32[(((size_t)(task * BB + m + 8) * DD) + n) >> 1] = pack_h2(v2, v3);
            }
        }
    } else {
        float scale = 1.0f;
        if (inte != nullptr) {
            const float* it = inte + task * EE;
            scale = it[0] + it[1] + it[2] + it[3];
        }
        float* Y = reinterpret_cast<float*>(Yo);
        #pragma unroll
        for (int mf = 0; mf < 4; ++mf) {
            const int m = m0 + wm * 64 + mf * 16 + er;
            #pragma unroll
            for (int nf = 0; nf < 4; ++nf) {
                const int n = n0 + wn * 32 + nf * 8 + ec;
                float2 b2 = *reinterpret_cast<const float2*>(bt + n);
                float2 v0, v1;
                v0.x = fmaxf(acc[mf][nf][0] + b2.x, 0.0f) * scale;
                v0.y = fmaxf(acc[mf][nf][1] + b2.y, 0.0f) * scale;
                v1.x = fmaxf(acc[mf][nf][2] + b2.x, 0.0f) * scale;
                v1.y = fmaxf(acc[mf][nf][3] + b2.y, 0.0f) * scale;
                *reinterpret_cast<float2*>(Y + ((size_t)m * TT + task) * DD + n) = v0;
                *reinterpret_cast<float2*>(Y + ((size_t)(m + 8) * TT + task) * DD + n) = v1;
            }
        }
    }
}

// ============================================================================
// Gate + combine. Output: fp32 [B][T][D] (outf) OR fp16 [T][B][D] (outh).
// ============================================================================
__global__ __launch_bounds__(128)
void gate_combine(const float* __restrict__ teo, const float* __restrict__ Wg,
                  const float* __restrict__ bg, float* __restrict__ outf,
                  fp16* __restrict__ outh)
{
    const int b = blockIdx.x;
    __shared__ float s_teo[TT][DD];
    __shared__ float s_g[TT][TT];

    const int tid  = threadIdx.x;
    const int warp = tid >> 5;
    const int lane = tid & 31;

    const size_t base = (size_t)b * TT * DD;
    for (int idx = tid; idx < TT * DD / 4; idx += 128) {
        reinterpret_cast<float4*>(&s_teo[0][0])[idx] =
            reinterpret_cast<const float4*>(teo + base)[idx];
    }
    __syncthreads();

    float a0 = 0.f, a1 = 0.f, a2 = 0.f, a3 = 0.f;
    for (int d = lane; d < DD; d += 32) {
        float v = s_teo[warp][d];
        float4 w = reinterpret_cast<const float4*>(Wg)[d];
        a0 = fmaf(v, w.x, a0);
        a1 = fmaf(v, w.y, a1);
        a2 = fmaf(v, w.z, a2);
        a3 = fmaf(v, w.w, a3);
    }
    #pragma unroll
    for (int off = 16; off; off >>= 1) {
        a0 += __shfl_xor_sync(0xffffffffu, a0, off);
        a1 += __shfl_xor_sync(0xffffffffu, a1, off);
        a2 += __shfl_xor_sync(0xffffffffu, a2, off);
        a3 += __shfl_xor_sync(0xffffffffu, a3, off);
    }
    if (lane == 0) {
        float l0 = a0 + bg[0], l1 = a1 + bg[1], l2 = a2 + bg[2], l3 = a3 + bg[3];
        float m = fmaxf(fmaxf(l0, l1), fmaxf(l2, l3));
        float e0 = __expf(l0 - m), e1 = __expf(l1 - m);
        float e2 = __expf(l2 - m), e3 = __expf(l3 - m);
        float inv = 1.0f / (e0 + e1 + e2 + e3);
        s_g[warp][0] = e0 * inv;
        s_g[warp][1] = e1 * inv;
        s_g[warp][2] = e2 * inv;
        s_g[warp][3] = e3 * inv;
    }
    __syncthreads();

    #pragma unroll
    for (int t = 0; t < TT; t++) {
        const float g0 = s_g[t][0], g1 = s_g[t][1], g2 = s_g[t][2], g3 = s_g[t][3];
        for (int d2 = tid; d2 < DD / 2; d2 += 128) {
            const int d = d2 * 2;
            float r0 = s_teo[t][d], r1 = s_teo[t][d + 1];
            r0 = fmaf(g0, s_teo[0][d], r0);     r1 = fmaf(g0, s_teo[0][d+1], r1);
            r0 = fmaf(g1, s_teo[1][d], r0);     r1 = fmaf(g1, s_teo[1][d+1], r1);
            r0 = fmaf(g2, s_teo[2][d], r0);     r1 = fmaf(g2, s_teo[2][d+1], r1);
            r0 = fmaf(g3, s_teo[3][d], r0);     r1 = fmaf(g3, s_teo[3][d+1], r1);
            if (outf != nullptr) {
                float2 v; v.x = r0; v.y = r1;
                *reinterpret_cast<float2*>(outf + base + (size_t)t * DD + d) = v;
            } else {
                size_t o = (((size_t)(t * BB + b) * DD) + d) >> 1;
                reinterpret_cast<uint32_t*>(outh)[o] = pack_h2(r0, r1);
            }
        }
    }
}

// ============================================================================
// launch
// ============================================================================
extern "C" void kernel_launch(void* const* d_in, const int* in_sizes, int n_in,
                              void* d_out, int out_size)
{
    const float* x    = (const float*)d_in[0];
    const float* W1   = (const float*)d_in[1];
    const float* b1   = (const float*)d_in[2];
    const float* W2   = (const float*)d_in[3];
    const float* b2   = (const float*)d_in[4];
    const float* inte = (const float*)d_in[5];
    const float* Wg   = (const float*)d_in[6];
    const float* bg   = (const float*)d_in[7];
    float* out = (float*)d_out;

    cudaFuncSetAttribute(gemm_pre<0>, cudaFuncAttributeMaxDynamicSharedMemorySize,
                         SMEM_TOTAL);
    cudaFuncSetAttribute(gemm_pre<1>, cudaFuncAttributeMaxDynamicSharedMemorySize,
                         SMEM_TOTAL);

    fp16 *ain, *t1, *w1h, *w1l, *w2h, *w2l;
    float* teo;
    cudaGetSymbolAddress((void**)&ain, g_in);
    cudaGetSymbolAddress((void**)&t1,  g_t1);
    cudaGetSymbolAddress((void**)&w1h, g_w1h);
    cudaGetSymbolAddress((void**)&w1l, g_w1l);
    cudaGetSymbolAddress((void**)&w2h, g_w2h);
    cudaGetSymbolAddress((void**)&w2l, g_w2l);
    cudaGetSymbolAddress((void**)&teo, g_teo);

    split_act<<<(BB * TT * DD / 2) / 256, 256>>>(x, ain);

    dim3 ggrid(DD / BN, BB / BM, TT);             // (8, 32, 4)
    dim3 wgrid(DD / 32, DD / 32, 2 * TT);         // (32, 32, 8)
    dim3 wblk(32, 8);

    for (int l = 0; l < LL; l++) {
        const float* W1l = W1 + (size_t)l * TT * DD * DD;
        const float* b1l = b1 + (size_t)l * TT * DD;
        const float* W2l = W2 + (size_t)l * TT * DD * DD;
        const float* b2l = b2 + (size_t)l * TT * DD;
        const float* il  = inte + (size_t)l * TT * EE;
        const float* Wgl = Wg + (size_t)l * DD * TT;
        const float* bgl = bg + (size_t)l * TT;

        split_w<<<wgrid, wblk>>>(W1l, W2l, w1h, w1l, w2h, w2l);

        gemm_pre<0><<<ggrid, 256, SMEM_TOTAL>>>(ain, w1h, w1l, b1l, nullptr, t1);
        gemm_pre<1><<<ggrid, 256, SMEM_TOTAL>>>(t1, w2h, w2l, b2l, il, teo);

        if (l == LL - 1)
            gate_combine<<<BB, 128>>>(teo, Wgl, bgl, out, nullptr);
        else
            gate_combine<<<BB, 128>>>(teo, Wgl, bgl, nullptr, ain);
    }
}